// round 1
// baseline (speedup 1.0000x reference)
#include <cuda_runtime.h>

// Problem constants
constexpr int Bc = 8;
constexpr int Nc = 512;
constexpr int Tc = 48;
constexpr int Dc = 128;
constexpr int NHc = 8;
constexpr int DKc = 16;
constexpr int BNc = Bc * Nc;         // 4096 blocks
constexpr int TDc = Tc * Dc;         // 6144 floats per (b,n) tile

// Scratch for conv outputs (q, k) — static device arrays (no allocation)
__device__ float g_q[(size_t)BNc * TDc];
__device__ float g_k[(size_t)BNc * TDc];

// ---------------------------------------------------------------------------
// Conv kernel: out[t, dout] = bias[dout] + sum_{j=0..2, din} in[t - pad + j, din] * w[j, din, dout]
// Segment-local ([0,12),[12,24),[24,48)) zero padding handled via a 60-row
// zero-padded smem input layout: padded_row(t') = t' + 2 + 4*seg. Out-of-segment
// reads land in zero rows => branch-free inner loop.
// OFFB = 0 : q conv (pad_l=2, causal), writes g_q
// OFFB = 1 : k conv (pad_l=1, same),   writes g_k
// ---------------------------------------------------------------------------
constexpr int CONV_SMEM_FLOATS = 3 * Dc * Dc + 60 * Dc;   // 49152 + 7680
constexpr int CONV_SMEM_BYTES  = CONV_SMEM_FLOATS * 4;    // 227328 B

__device__ __forceinline__ int seg_of(int t) { return (t < 12) ? 0 : ((t < 24) ? 1 : 2); }

template <int OFFB>
__global__ __launch_bounds__(256, 1)
void conv_kernel(const float* __restrict__ in, const float* __restrict__ w,
                 const float* __restrict__ bias)
{
    extern __shared__ float smem[];
    float* sW  = smem;               // [3][128][128]
    float* sIn = smem + 3 * Dc * Dc; // [60][128] padded rows

    const int tid = threadIdx.x;
    const int bn  = blockIdx.x;
    const float* inp  = in + (size_t)bn * TDc;
    float*       outp = (OFFB == 0 ? g_q : g_k) + (size_t)bn * TDc;

    // Stage weights (192KB) + zero-fill padded input
    {
        const float4* src = (const float4*)w;
        float4* dst = (float4*)sW;
        #pragma unroll 4
        for (int i = tid; i < 3 * Dc * Dc / 4; i += 256) dst[i] = src[i];
    }
    for (int i = tid; i < 60 * Dc; i += 256) sIn[i] = 0.f;
    __syncthreads();
    // Scatter real rows into padded layout
    {
        const float4* src = (const float4*)inp;
        for (int i = tid; i < TDc / 4; i += 256) {
            int t  = i >> 5;     // 32 float4 per row
            int c  = i & 31;
            int sg = seg_of(t);
            ((float4*)(sIn + (t + 2 + 4 * sg) * Dc))[c] = src[i];
        }
    }
    __syncthreads();

    const int dg    = tid & 31;   // dout group: dout = dg*4 .. dg*4+3
    const int tg    = tid >> 5;   // 8 groups of 6 t-values (each within ONE segment)
    const int tbase = tg * 6;
    const int sg    = seg_of(tbase);
    // Row for t' = tbase - 2 in padded layout
    const float* sx = sIn + (tbase + 4 * sg) * Dc;
    const float4* sw4 = (const float4*)sW;

    float4 acc[6];
    #pragma unroll
    for (int i = 0; i < 6; i++) acc[i] = make_float4(0.f, 0.f, 0.f, 0.f);

    #pragma unroll 4
    for (int din = 0; din < Dc; din++) {
        float xv[9];
        #pragma unroll
        for (int m = 0; m < 9; m++) xv[m] = sx[m * Dc + din];   // broadcast LDS
        float4 w0 = sw4[(0 * Dc + din) * 32 + dg];
        float4 w1 = sw4[(1 * Dc + din) * 32 + dg];
        float4 w2 = sw4[(2 * Dc + din) * 32 + dg];
        #pragma unroll
        for (int i = 0; i < 6; i++) {
            float a = xv[i + OFFB];
            float b = xv[i + OFFB + 1];
            float c = xv[i + OFFB + 2];
            acc[i].x += a * w0.x + b * w1.x + c * w2.x;
            acc[i].y += a * w0.y + b * w1.y + c * w2.y;
            acc[i].z += a * w0.z + b * w1.z + c * w2.z;
            acc[i].w += a * w0.w + b * w1.w + c * w2.w;
        }
    }

    float4 bb = *(const float4*)(bias + dg * 4);
    #pragma unroll
    for (int i = 0; i < 6; i++) {
        float4 r = acc[i];
        r.x += bb.x; r.y += bb.y; r.z += bb.z; r.w += bb.w;
        ((float4*)(outp + (tbase + i) * Dc))[dg] = r;
    }
}

// ---------------------------------------------------------------------------
// Fused attention kernel, one CTA per (b,n):
//   v = value @ v_w + v_b          (smem-staged weight)
//   scores_h = (q_h @ k_h^T)/4, causal softmax  (all 8 heads)
//   x = p @ v
//   out = x @ o_w + o_b
// smem strides chosen conflict-free per access pattern.
// ---------------------------------------------------------------------------
constexpr int SK_OFF   = 6144;                  // sA: 48x128 (stride 128)
constexpr int SK_STR   = 129;                   // sK: 48x129 (lane-row reads)
constexpr int SV_OFF   = SK_OFF + Tc * SK_STR;  // 12336
constexpr int SV_STR   = 132;
constexpr int SX_OFF   = SV_OFF + Tc * SV_STR;  // 18672
constexpr int SW_OFF   = SX_OFF + Tc * SV_STR;  // 25008  (sW 128x128 aliases sP)
constexpr int SP_PLANE = 2353;                  // 48x49 + 1 (plane-stride %32 = 17)
constexpr int ATTN_SMEM_FLOATS = SW_OFF + NHc * SP_PLANE;  // 43832
constexpr int ATTN_SMEM_BYTES  = ATTN_SMEM_FLOATS * 4;     // 175328 B

__global__ __launch_bounds__(256, 1)
void attn_kernel(const float* __restrict__ value,
                 const float* __restrict__ vw, const float* __restrict__ vb,
                 const float* __restrict__ ow, const float* __restrict__ ob,
                 float* __restrict__ out)
{
    extern __shared__ float s[];
    float* sA = s;            // value tile, then q tile (stride 128)
    float* sK = s + SK_OFF;   // k tile (stride 129)
    float* sV = s + SV_OFF;   // projected v (stride 132)
    float* sX = s + SX_OFF;   // attention output (stride 132)
    float* sW = s + SW_OFF;   // weight (v_w then o_w); aliases sP
    float* sP = sW;           // probs: 8 planes of 48x49, plane stride 2353

    const int tid  = threadIdx.x;
    const size_t bn = blockIdx.x;
    const int dg   = tid & 31;
    const int tg   = tid >> 5;
    const int tb   = tg * 6;
    const int lane = dg;
    const int wrp  = tg;

    // Phase 0: stage v_w + value tile
    for (int i = tid; i < Dc * Dc / 4; i += 256) ((float4*)sW)[i] = ((const float4*)vw)[i];
    for (int i = tid; i < TDc / 4; i += 256)
        ((float4*)sA)[i] = ((const float4*)(value + bn * TDc))[i];
    __syncthreads();

    // Phase 1: v projection -> sV
    {
        float4 acc[6];
        #pragma unroll
        for (int i = 0; i < 6; i++) acc[i] = make_float4(0.f, 0.f, 0.f, 0.f);
        #pragma unroll 4
        for (int d = 0; d < Dc; d++) {
            float4 w4 = ((const float4*)sW)[d * 32 + dg];
            #pragma unroll
            for (int i = 0; i < 6; i++) {
                float x = sA[(tb + i) * Dc + d];
                acc[i].x += x * w4.x; acc[i].y += x * w4.y;
                acc[i].z += x * w4.z; acc[i].w += x * w4.w;
            }
        }
        float4 bb = *(const float4*)(vb + dg * 4);
        #pragma unroll
        for (int i = 0; i < 6; i++) {
            acc[i].x += bb.x; acc[i].y += bb.y; acc[i].z += bb.z; acc[i].w += bb.w;
            *(float4*)(sV + (tb + i) * SV_STR + dg * 4) = acc[i];
        }
    }
    __syncthreads();

    // Phase 2: load q (stride 128) and k (stride 129)
    for (int i = tid; i < TDc / 4; i += 256)
        ((float4*)sA)[i] = ((const float4*)(g_q + bn * TDc))[i];
    for (int i = tid; i < TDc; i += 256) {
        int t = i >> 7, c = i & 127;
        sK[t * SK_STR + c] = g_k[bn * TDc + i];
    }
    __syncthreads();

    // Phase 3: scores (all heads) -> sP
    for (int h = 0; h < NHc; h++) {
        float a0[6], a1[6];
        #pragma unroll
        for (int r = 0; r < 6; r++) { a0[r] = 0.f; a1[r] = 0.f; }
        const int u0 = lane, u1 = lane + 32;
        #pragma unroll
        for (int dk = 0; dk < DKc; dk++) {
            int c = h * DKc + dk;
            float k0 = sK[u0 * SK_STR + c];
            float k1 = (u1 < Tc) ? sK[u1 * SK_STR + c] : 0.f;
            #pragma unroll
            for (int r = 0; r < 6; r++) {
                float qv = sA[(wrp + 8 * r) * Dc + c];   // warp-uniform broadcast
                a0[r] += qv * k0;
                a1[r] += qv * k1;
            }
        }
        float* plane = sP + h * SP_PLANE;
        #pragma unroll
        for (int r = 0; r < 6; r++) {
            int t = wrp + 8 * r;
            plane[t * 49 + u0] = a0[r] * 0.25f;
            if (u1 < Tc) plane[t * 49 + u1] = a1[r] * 0.25f;
        }
    }
    __syncthreads();

    // Phase 4: causal softmax in place (row per thread)
    for (int rid = tid; rid < NHc * Tc; rid += 256) {
        int h = rid / Tc, t = rid % Tc;
        float* row = sP + h * SP_PLANE + t * 49;
        float mx = row[0];
        for (int u = 1; u <= t; u++) mx = fmaxf(mx, row[u]);
        float sum = 0.f;
        for (int u = 0; u <= t; u++) { float e = __expf(row[u] - mx); row[u] = e; sum += e; }
        float inv = 1.f / sum;
        for (int u = 0; u <= t; u++) row[u] *= inv;
        for (int u = t + 1; u < Tc; u++) row[u] = 0.f;
    }
    __syncthreads();

    // Phase 5: x = p @ v -> sX  (head h owns d in [16h, 16h+16))
    {
        const int d4 = dg * 4;
        const int h  = dg >> 2;
        const float* plane = sP + h * SP_PLANE;
        float4 acc[6];
        #pragma unroll
        for (int i = 0; i < 6; i++) acc[i] = make_float4(0.f, 0.f, 0.f, 0.f);
        #pragma unroll 2
        for (int u = 0; u < Tc; u++) {
            float4 v4 = *(const float4*)(sV + u * SV_STR + d4);
            #pragma unroll
            for (int i = 0; i < 6; i++) {
                float p = plane[(tb + i) * 49 + u];
                acc[i].x += p * v4.x; acc[i].y += p * v4.y;
                acc[i].z += p * v4.z; acc[i].w += p * v4.w;
            }
        }
        #pragma unroll
        for (int i = 0; i < 6; i++)
            *(float4*)(sX + (tb + i) * SV_STR + d4) = acc[i];
    }
    __syncthreads();

    // Phase 6: stage o_w (overwrites sP)
    for (int i = tid; i < Dc * Dc / 4; i += 256) ((float4*)sW)[i] = ((const float4*)ow)[i];
    __syncthreads();

    // Phase 7: out = x @ o_w + o_b
    {
        float4 acc[6];
        #pragma unroll
        for (int i = 0; i < 6; i++) acc[i] = make_float4(0.f, 0.f, 0.f, 0.f);
        #pragma unroll 4
        for (int d = 0; d < Dc; d++) {
            float4 w4 = ((const float4*)sW)[d * 32 + dg];
            #pragma unroll
            for (int i = 0; i < 6; i++) {
                float x = sX[(tb + i) * SV_STR + d];
                acc[i].x += x * w4.x; acc[i].y += x * w4.y;
                acc[i].z += x * w4.z; acc[i].w += x * w4.w;
            }
        }
        float4 bb = *(const float4*)(ob + dg * 4);
        #pragma unroll
        for (int i = 0; i < 6; i++) {
            acc[i].x += bb.x; acc[i].y += bb.y; acc[i].z += bb.z; acc[i].w += bb.w;
            ((float4*)(out + bn * TDc + (tb + i) * Dc))[dg] = acc[i];
        }
    }
}

// ---------------------------------------------------------------------------
extern "C" void kernel_launch(void* const* d_in, const int* in_sizes, int n_in,
                              void* d_out, int out_size)
{
    (void)in_sizes; (void)n_in; (void)out_size;
    const float* query = (const float*)d_in[0];
    const float* key_t = (const float*)d_in[1];
    const float* value = (const float*)d_in[2];
    // d_in[3] = mask (B,T,T) int32 tril — equivalent to causal; applied analytically
    const float* qw = (const float*)d_in[4];
    const float* qb = (const float*)d_in[5];
    const float* kw = (const float*)d_in[6];
    const float* kb = (const float*)d_in[7];
    const float* vw = (const float*)d_in[8];
    const float* vb = (const float*)d_in[9];
    const float* ow = (const float*)d_in[10];
    const float* ob = (const float*)d_in[11];
    float* out = (float*)d_out;

    cudaFuncSetAttribute(conv_kernel<0>, cudaFuncAttributeMaxDynamicSharedMemorySize, CONV_SMEM_BYTES);
    cudaFuncSetAttribute(conv_kernel<1>, cudaFuncAttributeMaxDynamicSharedMemorySize, CONV_SMEM_BYTES);
    cudaFuncSetAttribute(attn_kernel,    cudaFuncAttributeMaxDynamicSharedMemorySize, ATTN_SMEM_BYTES);

    conv_kernel<0><<<BNc, 256, CONV_SMEM_BYTES>>>(query, qw, qb);   // causal q conv -> g_q
    conv_kernel<1><<<BNc, 256, CONV_SMEM_BYTES>>>(key_t, kw, kb);   // same-pad k conv -> g_k
    attn_kernel<<<BNc, 256, ATTN_SMEM_BYTES>>>(value, vw, vb, ow, ob, out);
}

// round 3
// speedup vs baseline: 1.4797x; 1.4797x over previous
#include <cuda_runtime.h>
#include <cuda_fp16.h>
#include <cstdint>

// Problem constants
constexpr int Bc = 8;
constexpr int Nc = 512;
constexpr int Tc = 48;
constexpr int Dc = 128;
constexpr int NHc = 8;
constexpr int DKc = 16;
constexpr int BNc = Bc * Nc;         // 4096 tiles
constexpr int TDc = Tc * Dc;         // 6144 floats per (b,n) tile

// Scratch: conv outputs + pre-transposed fp16 weights Wt[dout][k], k=j*128+din
__device__ float  g_q[(size_t)BNc * TDc];
__device__ float  g_k[(size_t)BNc * TDc];
__device__ __half g_wtq[128 * 384];
__device__ __half g_wtk[128 * 384];

__device__ __forceinline__ uint32_t smem_u32(const void* p) {
    uint32_t a;
    asm("{ .reg .u64 t; cvta.to.shared.u64 t, %1; cvt.u32.u64 %0, t; }" : "=r"(a) : "l"(p));
    return a;
}
__device__ __forceinline__ void ldsm_x4(uint32_t* r, uint32_t a) {
    asm volatile("ldmatrix.sync.aligned.m8n8.x4.shared.b16 {%0,%1,%2,%3}, [%4];"
                 : "=r"(r[0]), "=r"(r[1]), "=r"(r[2]), "=r"(r[3]) : "r"(a));
}
__device__ __forceinline__ void ldsm_x2(uint32_t* r, uint32_t a) {
    asm volatile("ldmatrix.sync.aligned.m8n8.x2.shared.b16 {%0,%1}, [%2];"
                 : "=r"(r[0]), "=r"(r[1]) : "r"(a));
}
__device__ __forceinline__ void mma16816(float* c, const uint32_t* a, const uint32_t* b) {
    asm volatile("mma.sync.aligned.m16n8k16.row.col.f32.f16.f16.f32 "
                 "{%0,%1,%2,%3}, {%4,%5,%6,%7}, {%8,%9}, {%0,%1,%2,%3};"
                 : "+f"(c[0]), "+f"(c[1]), "+f"(c[2]), "+f"(c[3])
                 : "r"(a[0]), "r"(a[1]), "r"(a[2]), "r"(a[3]), "r"(b[0]), "r"(b[1]));
}

__device__ __forceinline__ int seg_of(int t) { return (t < 12) ? 0 : ((t < 24) ? 1 : 2); }

// ===========================================================================
// Weight prep: Wt[dout][j*128+din] = w[j][din][dout], fp16
// ===========================================================================
__global__ void prep_w_kernel(const float* __restrict__ w, __half* __restrict__ out) {
    int i = blockIdx.x * blockDim.x + threadIdx.x;
    if (i < 128 * 384) {
        int dout = i / 384, k = i % 384;
        int j = k >> 7, din = k & 127;
        out[i] = __float2half(w[(j * 128 + din) * 128 + dout]);
    }
}

// ===========================================================================
// mma.sync conv kernel. One CTA = two (b,n) tiles.
// GEMM: out[96,128] = X[96,384] @ Wt[128,384]^T
//   X rows 0-47 = tile0 t, rows 48-95 = tile1 t (no padding rows).
//   X[row, j*128+din] = in[src,din] if src=t+j-(2-OFFB) within t's segment else 0.
// smem layouts (fp16, row stride 392 halfs = 784 B => ldmatrix conflict-free):
//   sX: 96 x 392, sW: 128 x 392 (Wt rows, n-major = B-fragment layout for
//   ldmatrix.x2 non-trans).
// 6 warps compute m16 blocks; 16 n-tiles x 24 k-steps of m16n8k16.
// ===========================================================================
constexpr int XSTR_B  = 784;                       // row stride bytes
constexpr int CV_X    = 0;
constexpr int CV_W    = 96 * XSTR_B;               // 75264
constexpr int CV_B    = CV_W + 128 * XSTR_B;       // 175616
constexpr int CV_SMEM = CV_B + 512;                // 176128 B

template <int OFFB>
__global__ __launch_bounds__(256, 1)
void conv_mma_kernel(const float* __restrict__ in, const __half* __restrict__ wt,
                     const float* __restrict__ bias, float* __restrict__ outbuf)
{
    extern __shared__ char smem[];
    const uint32_t sbase = smem_u32(smem);
    const int tid = threadIdx.x;
    const int wid = tid >> 5;
    const int lane = tid & 31;
    float* sB = (float*)(smem + CV_B);

    // Stage Wt rows (768 B each) into stride-784 layout
    #pragma unroll 4
    for (int c = tid; c < 128 * 48; c += 256) {
        int n = c / 48, ch = c % 48;
        uint4 v = *(const uint4*)((const char*)wt + n * 768 + ch * 16);
        *(uint4*)(smem + CV_W + n * XSTR_B + ch * 16) = v;
    }
    if (tid < 32) ((float4*)sB)[tid] = ((const float4*)bias)[tid];
    // Zero X
    {
        float4* xz = (float4*)(smem + CV_X);
        #pragma unroll 4
        for (int i = tid; i < 96 * XSTR_B / 16; i += 256) xz[i] = make_float4(0.f, 0.f, 0.f, 0.f);
    }
    __syncthreads();

    // Fill X (branch-free segment padding via predicated store)
    {
        const float* inp0 = in + (size_t)(blockIdx.x * 2) * TDc;
        for (int i = tid; i < 96 * 192; i += 256) {
            int row = i / 192, p = i - row * 192;
            int tile = row / 48, t = row - tile * 48;
            int j = p >> 6, dp = p & 63;
            int sg = seg_of(t);
            int s = (sg == 0) ? 0 : (sg == 1 ? 12 : 24);
            int e = (sg == 0) ? 12 : (sg == 1 ? 24 : 48);
            int src = t + j - (2 - OFFB);
            if (src >= s && src < e) {
                float2 v = *(const float2*)(inp0 + (size_t)tile * TDc + src * 128 + dp * 2);
                *(__half2*)(smem + CV_X + row * XSTR_B + (j * 128 + dp * 2) * 2) =
                    __floats2half2_rn(v.x, v.y);
            }
        }
    }
    __syncthreads();

    if (wid < 6) {
        const int m0 = wid * 16;
        float acc[16][4];
        #pragma unroll
        for (int nt = 0; nt < 16; nt++)
            #pragma unroll
            for (int q = 0; q < 4; q++) acc[nt][q] = 0.f;

        // A fragment address: row m0+(lane%16), k-col block (lane/16)*8 halfs
        const uint32_t aaddr = sbase + CV_X + (m0 + (lane & 15)) * XSTR_B + (lane >> 4) * 16;
        // B fragment address base: row n=(lane&7), k-col block ((lane>>3)&1)*8 halfs
        const uint32_t baddr0 = sbase + CV_W + (lane & 7) * XSTR_B + ((lane >> 3) & 1) * 16;

        for (int ks = 0; ks < 24; ks++) {
            uint32_t a[4];
            ldsm_x4(a, aaddr + ks * 32);
            const uint32_t bk = baddr0 + ks * 32;
            #pragma unroll
            for (int nt = 0; nt < 16; nt++) {
                uint32_t b[2];
                ldsm_x2(b, bk + nt * 8 * XSTR_B);
                mma16816(acc[nt], a, b);
            }
        }

        // Epilogue: C frag -> global with bias. Rows r=m0+lane/4 and r+8.
        const int r    = m0 + (lane >> 2);
        const int tile = m0 >= 48 ? 1 : 0;
        const int t0   = r - tile * 48;
        float* op = outbuf + (size_t)(blockIdx.x * 2 + tile) * TDc;
        const int cbase = (lane & 3) * 2;
        #pragma unroll
        for (int nt = 0; nt < 16; nt++) {
            int col = nt * 8 + cbase;
            float2 b2 = *(const float2*)(sB + col);
            float2 o0 = make_float2(acc[nt][0] + b2.x, acc[nt][1] + b2.y);
            float2 o1 = make_float2(acc[nt][2] + b2.x, acc[nt][3] + b2.y);
            *(float2*)(op + t0 * 128 + col)       = o0;
            *(float2*)(op + (t0 + 8) * 128 + col) = o1;
        }
    }
}

// ===========================================================================
// Fused attention kernel (unchanged from R1 — passing), one CTA per (b,n).
// ===========================================================================
constexpr int SK_OFF   = 6144;
constexpr int SK_STR   = 129;
constexpr int SV_OFF   = SK_OFF + Tc * SK_STR;
constexpr int SV_STR   = 132;
constexpr int SX_OFF   = SV_OFF + Tc * SV_STR;
constexpr int SW_OFF   = SX_OFF + Tc * SV_STR;
constexpr int SP_PLANE = 2353;
constexpr int ATTN_SMEM_FLOATS = SW_OFF + NHc * SP_PLANE;
constexpr int ATTN_SMEM_BYTES  = ATTN_SMEM_FLOATS * 4;

__global__ __launch_bounds__(256, 1)
void attn_kernel(const float* __restrict__ value,
                 const float* __restrict__ vw, const float* __restrict__ vb,
                 const float* __restrict__ ow, const float* __restrict__ ob,
                 float* __restrict__ out)
{
    extern __shared__ float s[];
    float* sA = s;
    float* sK = s + SK_OFF;
    float* sV = s + SV_OFF;
    float* sX = s + SX_OFF;
    float* sW = s + SW_OFF;
    float* sP = sW;

    const int tid  = threadIdx.x;
    const size_t bn = blockIdx.x;
    const int dg   = tid & 31;
    const int tg   = tid >> 5;
    const int tb   = tg * 6;
    const int lane = dg;
    const int wrp  = tg;

    for (int i = tid; i < Dc * Dc / 4; i += 256) ((float4*)sW)[i] = ((const float4*)vw)[i];
    for (int i = tid; i < TDc / 4; i += 256)
        ((float4*)sA)[i] = ((const float4*)(value + bn * TDc))[i];
    __syncthreads();

    {
        float4 acc[6];
        #pragma unroll
        for (int i = 0; i < 6; i++) acc[i] = make_float4(0.f, 0.f, 0.f, 0.f);
        #pragma unroll 4
        for (int d = 0; d < Dc; d++) {
            float4 w4 = ((const float4*)sW)[d * 32 + dg];
            #pragma unroll
            for (int i = 0; i < 6; i++) {
                float x = sA[(tb + i) * Dc + d];
                acc[i].x += x * w4.x; acc[i].y += x * w4.y;
                acc[i].z += x * w4.z; acc[i].w += x * w4.w;
            }
        }
        float4 bb = *(const float4*)(vb + dg * 4);
        #pragma unroll
        for (int i = 0; i < 6; i++) {
            acc[i].x += bb.x; acc[i].y += bb.y; acc[i].z += bb.z; acc[i].w += bb.w;
            *(float4*)(sV + (tb + i) * SV_STR + dg * 4) = acc[i];
        }
    }
    __syncthreads();

    for (int i = tid; i < TDc / 4; i += 256)
        ((float4*)sA)[i] = ((const float4*)(g_q + bn * TDc))[i];
    for (int i = tid; i < TDc; i += 256) {
        int t = i >> 7, c = i & 127;
        sK[t * SK_STR + c] = g_k[bn * TDc + i];
    }
    __syncthreads();

    for (int h = 0; h < NHc; h++) {
        float a0[6], a1[6];
        #pragma unroll
        for (int r = 0; r < 6; r++) { a0[r] = 0.f; a1[r] = 0.f; }
        const int u0 = lane, u1 = lane + 32;
        #pragma unroll
        for (int dk = 0; dk < DKc; dk++) {
            int c = h * DKc + dk;
            float k0 = sK[u0 * SK_STR + c];
            float k1 = (u1 < Tc) ? sK[u1 * SK_STR + c] : 0.f;
            #pragma unroll
            for (int r = 0; r < 6; r++) {
                float qv = sA[(wrp + 8 * r) * Dc + c];
                a0[r] += qv * k0;
                a1[r] += qv * k1;
            }
        }
        float* plane = sP + h * SP_PLANE;
        #pragma unroll
        for (int r = 0; r < 6; r++) {
            int t = wrp + 8 * r;
            plane[t * 49 + u0] = a0[r] * 0.25f;
            if (u1 < Tc) plane[t * 49 + u1] = a1[r] * 0.25f;
        }
    }
    __syncthreads();

    for (int rid = tid; rid < NHc * Tc; rid += 256) {
        int h = rid / Tc, t = rid % Tc;
        float* row = sP + h * SP_PLANE + t * 49;
        float mx = row[0];
        for (int u = 1; u <= t; u++) mx = fmaxf(mx, row[u]);
        float sum = 0.f;
        for (int u = 0; u <= t; u++) { float e = __expf(row[u] - mx); row[u] = e; sum += e; }
        float inv = 1.f / sum;
        for (int u = 0; u <= t; u++) row[u] *= inv;
        for (int u = t + 1; u < Tc; u++) row[u] = 0.f;
    }
    __syncthreads();

    {
        const int d4 = dg * 4;
        const int h  = dg >> 2;
        const float* plane = sP + h * SP_PLANE;
        float4 acc[6];
        #pragma unroll
        for (int i = 0; i < 6; i++) acc[i] = make_float4(0.f, 0.f, 0.f, 0.f);
        #pragma unroll 2
        for (int u = 0; u < Tc; u++) {
            float4 v4 = *(const float4*)(sV + u * SV_STR + d4);
            #pragma unroll
            for (int i = 0; i < 6; i++) {
                float p = plane[(tb + i) * 49 + u];
                acc[i].x += p * v4.x; acc[i].y += p * v4.y;
                acc[i].z += p * v4.z; acc[i].w += p * v4.w;
            }
        }
        #pragma unroll
        for (int i = 0; i < 6; i++)
            *(float4*)(sX + (tb + i) * SV_STR + d4) = acc[i];
    }
    __syncthreads();

    for (int i = tid; i < Dc * Dc / 4; i += 256) ((float4*)sW)[i] = ((const float4*)ow)[i];
    __syncthreads();

    {
        float4 acc[6];
        #pragma unroll
        for (int i = 0; i < 6; i++) acc[i] = make_float4(0.f, 0.f, 0.f, 0.f);
        #pragma unroll 4
        for (int d = 0; d < Dc; d++) {
            float4 w4 = ((const float4*)sW)[d * 32 + dg];
            #pragma unroll
            for (int i = 0; i < 6; i++) {
                float x = sX[(tb + i) * SV_STR + d];
                acc[i].x += x * w4.x; acc[i].y += x * w4.y;
                acc[i].z += x * w4.z; acc[i].w += x * w4.w;
            }
        }
        float4 bb = *(const float4*)(ob + dg * 4);
        #pragma unroll
        for (int i = 0; i < 6; i++) {
            acc[i].x += bb.x; acc[i].y += bb.y; acc[i].z += bb.z; acc[i].w += bb.w;
            ((float4*)(out + bn * TDc + (tb + i) * Dc))[dg] = acc[i];
        }
    }
}

// ===========================================================================
extern "C" void kernel_launch(void* const* d_in, const int* in_sizes, int n_in,
                              void* d_out, int out_size)
{
    (void)in_sizes; (void)n_in; (void)out_size;
    const float* query = (const float*)d_in[0];
    const float* key_t = (const float*)d_in[1];
    const float* value = (const float*)d_in[2];
    const float* qw = (const float*)d_in[4];
    const float* qb = (const float*)d_in[5];
    const float* kw = (const float*)d_in[6];
    const float* kb = (const float*)d_in[7];
    const float* vw = (const float*)d_in[8];
    const float* vb = (const float*)d_in[9];
    const float* ow = (const float*)d_in[10];
    const float* ob = (const float*)d_in[11];
    float* out = (float*)d_out;

    __half* wtq; cudaGetSymbolAddress((void**)&wtq, g_wtq);
    __half* wtk; cudaGetSymbolAddress((void**)&wtk, g_wtk);
    float*  gq;  cudaGetSymbolAddress((void**)&gq,  g_q);
    float*  gk;  cudaGetSymbolAddress((void**)&gk,  g_k);

    cudaFuncSetAttribute(conv_mma_kernel<0>, cudaFuncAttributeMaxDynamicSharedMemorySize, CV_SMEM);
    cudaFuncSetAttribute(conv_mma_kernel<1>, cudaFuncAttributeMaxDynamicSharedMemorySize, CV_SMEM);
    cudaFuncSetAttribute(attn_kernel,        cudaFuncAttributeMaxDynamicSharedMemorySize, ATTN_SMEM_BYTES);

    prep_w_kernel<<<192, 256>>>(qw, wtq);
    prep_w_kernel<<<192, 256>>>(kw, wtk);
    conv_mma_kernel<0><<<BNc / 2, 256, CV_SMEM>>>(query, wtq, qb, gq);
    conv_mma_kernel<1><<<BNc / 2, 256, CV_SMEM>>>(key_t, wtk, kb, gk);
    attn_kernel<<<BNc, 256, ATTN_SMEM_BYTES>>>(value, vw, vb, ow, ob, out);
}

// round 4
// speedup vs baseline: 2.4220x; 1.6368x over previous
#include <cuda_runtime.h>
#include <cuda_fp16.h>
#include <cstdint>

// Problem constants
constexpr int Bc = 8;
constexpr int Nc = 512;
constexpr int Tc = 48;
constexpr int Dc = 128;
constexpr int NHc = 8;
constexpr int BNc = Bc * Nc;         // 4096 tiles
constexpr int TDc = Tc * Dc;         // 6144 elems per (b,n) tile

// Scratch: fp16 conv outputs + pre-transposed fp16 weights
__device__ __half g_q[(size_t)BNc * TDc];
__device__ __half g_k[(size_t)BNc * TDc];
__device__ __half g_wtq[128 * 384];   // conv Wt[dout][k], k=j*128+din
__device__ __half g_wtk[128 * 384];
__device__ __half g_vwt[128 * 128];   // proj Wt[n][k] = w[k][n]
__device__ __half g_owt[128 * 128];

__device__ __forceinline__ uint32_t smem_u32(const void* p) {
    uint32_t a;
    asm("{ .reg .u64 t; cvta.to.shared.u64 t, %1; cvt.u32.u64 %0, t; }" : "=r"(a) : "l"(p));
    return a;
}
__device__ __forceinline__ void ldsm_x4(uint32_t* r, uint32_t a) {
    asm volatile("ldmatrix.sync.aligned.m8n8.x4.shared.b16 {%0,%1,%2,%3}, [%4];"
                 : "=r"(r[0]), "=r"(r[1]), "=r"(r[2]), "=r"(r[3]) : "r"(a));
}
__device__ __forceinline__ void ldsm_x4_trans(uint32_t* r, uint32_t a) {
    asm volatile("ldmatrix.sync.aligned.m8n8.x4.trans.shared.b16 {%0,%1,%2,%3}, [%4];"
                 : "=r"(r[0]), "=r"(r[1]), "=r"(r[2]), "=r"(r[3]) : "r"(a));
}
__device__ __forceinline__ void mma16816(float* c, const uint32_t* a, const uint32_t* b) {
    asm volatile("mma.sync.aligned.m16n8k16.row.col.f32.f16.f16.f32 "
                 "{%0,%1,%2,%3}, {%4,%5,%6,%7}, {%8,%9}, {%0,%1,%2,%3};"
                 : "+f"(c[0]), "+f"(c[1]), "+f"(c[2]), "+f"(c[3])
                 : "r"(a[0]), "r"(a[1]), "r"(a[2]), "r"(a[3]), "r"(b[0]), "r"(b[1]));
}
__device__ __forceinline__ int seg_of(int t) { return (t < 12) ? 0 : ((t < 24) ? 1 : 2); }

// ===========================================================================
// Weight prep
// ===========================================================================
__global__ void prep_w_kernel(const float* __restrict__ w, __half* __restrict__ out) {
    int i = blockIdx.x * blockDim.x + threadIdx.x;
    if (i < 128 * 384) {
        int dout = i / 384, k = i % 384;
        int j = k >> 7, din = k & 127;
        out[i] = __float2half(w[(j * 128 + din) * 128 + dout]);
    }
}
__global__ void prep_proj_kernel(const float* __restrict__ w, __half* __restrict__ out) {
    int i = blockIdx.x * blockDim.x + threadIdx.x;
    if (i < 16384) { int n = i >> 7, k = i & 127; out[i] = __float2half(w[k * 128 + n]); }
}

// ===========================================================================
// mma.sync conv kernel. One CTA = one (b,n) tile x half of N (88 KB smem
// => 2 CTAs/SM). out[48, 64] = X[48,384] @ Wt_half^T, fp16 output.
// X[t, j*128+din] = in[src,din] if src=t+j-(2-OFFB) within t's segment, else 0
// (always-store fill; no zero pass). Row stride 784 B (conflict-free ldmatrix).
// ===========================================================================
constexpr int CXS   = 784;
constexpr int CV_X  = 0;                 // 48*784 = 37632
constexpr int CV_W  = 37632;             // 64*784 = 50176
constexpr int CV_SM = 87808;

template <int OFFB>
__global__ __launch_bounds__(256, 2)
void conv_mma_kernel(const float* __restrict__ in, const __half* __restrict__ wt,
                     const float* __restrict__ bias, __half* __restrict__ outbuf)
{
    extern __shared__ char sm[];
    const uint32_t sb = smem_u32(sm);
    const int tid = threadIdx.x, wid = tid >> 5, lane = tid & 31;
    const int tile = blockIdx.x >> 1;
    const int nb   = (blockIdx.x & 1) * 64;

    // Stage this CTA's 64 Wt rows (n-major, 768 B each) into stride-784
    #pragma unroll 4
    for (int c = tid; c < 64 * 48; c += 256) {
        int n = c / 48, ch = c % 48;
        uint4 v = *(const uint4*)((const char*)wt + (nb + n) * 768 + ch * 16);
        *(uint4*)(sm + CV_W + n * CXS + ch * 16) = v;
    }
    // Fill X (always-store: zero or converted value)
    {
        const float* inp = in + (size_t)tile * TDc;
        for (int i = tid; i < 48 * 192; i += 256) {
            int t = i / 192, p = i - t * 192;
            int j = p >> 6, dp = p & 63;
            int sg = seg_of(t);
            int s0 = (sg == 0) ? 0 : (sg == 1 ? 12 : 24);
            int e0 = (sg == 0) ? 12 : (sg == 1 ? 24 : 48);
            int src = t + j - (2 - OFFB);
            __half2 h = __floats2half2_rn(0.f, 0.f);
            if (src >= s0 && src < e0) {
                float2 v = *(const float2*)(inp + src * 128 + dp * 2);
                h = __floats2half2_rn(v.x, v.y);
            }
            *(__half2*)(sm + CV_X + t * CXS + (j * 128 + dp * 2) * 2) = h;
        }
    }
    __syncthreads();

    if (wid < 6) {
        for (int u = wid; u < 12; u += 6) {
            int mb = u >> 2, nc = u & 3;
            float acc[2][4] = {};
            uint32_t aaddr = sb + CV_X + (mb * 16 + (lane & 15)) * CXS + ((lane >> 4) * 8) * 2;
            uint32_t baddr = sb + CV_W + (nc * 16 + ((lane >> 4) << 3) + (lane & 7)) * CXS
                             + (((lane >> 3) & 1) * 8) * 2;
            #pragma unroll 4
            for (int ks = 0; ks < 24; ks++) {
                uint32_t a[4], b[4];
                ldsm_x4(a, aaddr + ks * 32);
                ldsm_x4(b, baddr + ks * 32);
                mma16816(acc[0], a, b);
                mma16816(acc[1], a, b + 2);
            }
            int t0 = mb * 16 + (lane >> 2);
            __half* op = outbuf + (size_t)tile * TDc;
            #pragma unroll
            for (int f = 0; f < 2; f++) {
                int col = nb + nc * 16 + f * 8 + (lane & 3) * 2;
                float2 bb = *(const float2*)(bias + col);
                *(__half2*)(op + t0 * 128 + col) =
                    __floats2half2_rn(acc[f][0] + bb.x, acc[f][1] + bb.y);
                *(__half2*)(op + (t0 + 8) * 128 + col) =
                    __floats2half2_rn(acc[f][2] + bb.x, acc[f][3] + bb.y);
            }
        }
    }
}

// ===========================================================================
// Full-mma attention kernel, one CTA per (b,n), 111.25 KB smem => 2 CTAs/SM.
// Regions (fp16 tiles stride 272 B):
//   U1 [0,13056):      value -> q -> x      (time-aliased)
//   K  [13056,26112):  k tile
//   V  [26112,39168):  projected v (fp16)
//   R  [39168,112896): vw | fp32 scores (8 planes 48x48, stride 48 fl) +
//                      in-place fp16 probs (row stride 192 B) | ow
//   BIAS [112896,113920): vb(128) + ob(128) fp32
// ===========================================================================
constexpr int AT_U1 = 0;
constexpr int AT_K  = 13056;
constexpr int AT_V  = 26112;
constexpr int AT_R  = 39168;
constexpr int AT_BIAS = AT_R + 73728;     // 112896
constexpr int AT_SMEM = AT_BIAS + 1024;   // 113920

__global__ __launch_bounds__(256, 2)
void attn_mma_kernel(const float* __restrict__ value,
                     const __half* __restrict__ vwt, const float* __restrict__ vb,
                     const __half* __restrict__ owt, const float* __restrict__ ob,
                     float* __restrict__ out)
{
    extern __shared__ char sm[];
    const uint32_t sb = smem_u32(sm);
    const int tid = threadIdx.x, wid = tid >> 5, lane = tid & 31;
    const size_t bn = blockIdx.x;
    float* sBias = (float*)(sm + AT_BIAS);

    // ---- P0: stage biases, vw, value(fp32->fp16), k ----
    sBias[tid] = (tid < 128) ? vb[tid] : ob[tid - 128];
    {
        const uint4* src = (const uint4*)vwt;
        #pragma unroll 2
        for (int c = tid; c < 2048; c += 256) {
            int r = c >> 4, o = c & 15;
            *(uint4*)(sm + AT_R + r * 272 + o * 16) = src[c];
        }
    }
    {
        const float2* src = (const float2*)(value + bn * TDc);
        #pragma unroll 2
        for (int i = tid; i < 3072; i += 256) {
            int r = i >> 6, c = i & 63;
            float2 v = src[i];
            *(__half2*)(sm + AT_U1 + r * 272 + c * 4) = __floats2half2_rn(v.x, v.y);
        }
    }
    {
        const uint4* src = (const uint4*)(g_k + bn * TDc);
        for (int c = tid; c < 768; c += 256) {
            int r = c >> 4, o = c & 15;
            *(uint4*)(sm + AT_K + r * 272 + o * 16) = src[c];
        }
    }
    __syncthreads();

    // ---- P1: v = value @ vw + vb  -> fp16 sV ----
    for (int u = wid; u < 24; u += 8) {
        int mb = u >> 3, n0 = (u & 7) * 16;
        float acc[2][4] = {};
        uint32_t aaddr = sb + AT_U1 + (mb * 16 + (lane & 15)) * 272 + ((lane >> 4) * 8) * 2;
        uint32_t baddr = sb + AT_R + (n0 + ((lane >> 4) << 3) + (lane & 7)) * 272
                         + (((lane >> 3) & 1) * 8) * 2;
        #pragma unroll
        for (int ks = 0; ks < 8; ks++) {
            uint32_t a[4], b[4];
            ldsm_x4(a, aaddr + ks * 32);
            ldsm_x4(b, baddr + ks * 32);
            mma16816(acc[0], a, b);
            mma16816(acc[1], a, b + 2);
        }
        int t0 = mb * 16 + (lane >> 2);
        #pragma unroll
        for (int f = 0; f < 2; f++) {
            int col = n0 + f * 8 + (lane & 3) * 2;
            float2 bb = *(const float2*)(sBias + col);
            *(__half2*)(sm + AT_V + t0 * 272 + col * 2) =
                __floats2half2_rn(acc[f][0] + bb.x, acc[f][1] + bb.y);
            *(__half2*)(sm + AT_V + (t0 + 8) * 272 + col * 2) =
                __floats2half2_rn(acc[f][2] + bb.x, acc[f][3] + bb.y);
        }
    }
    __syncthreads();

    // ---- P2: stage q (overwrites value) ----
    {
        const uint4* src = (const uint4*)(g_q + bn * TDc);
        for (int c = tid; c < 768; c += 256) {
            int r = c >> 4, o = c & 15;
            *(uint4*)(sm + AT_U1 + r * 272 + o * 16) = src[c];
        }
    }
    __syncthreads();

    // ---- P3: scores = (q_h @ k_h^T)/4 -> fp32 planes in R ----
    for (int u = wid; u < 24; u += 8) {
        int h = u / 3, mb = u % 3;
        float acc[6][4] = {};
        uint32_t a[4];
        ldsm_x4(a, sb + AT_U1 + (mb * 16 + (lane & 15)) * 272 + (h * 16 + (lane >> 4) * 8) * 2);
        #pragma unroll
        for (int np = 0; np < 3; np++) {
            uint32_t b[4];
            ldsm_x4(b, sb + AT_K + (np * 16 + ((lane >> 4) << 3) + (lane & 7)) * 272
                       + (h * 16 + ((lane >> 3) & 1) * 8) * 2);
            mma16816(acc[np * 2], a, b);
            mma16816(acc[np * 2 + 1], a, b + 2);
        }
        float* plane = (float*)(sm + AT_R) + h * 2304;
        int t0 = mb * 16 + (lane >> 2);
        #pragma unroll
        for (int f = 0; f < 6; f++) {
            int s0 = (f >> 1) * 16 + (f & 1) * 8 + (lane & 3) * 2;
            *(float2*)(plane + t0 * 48 + s0) = make_float2(acc[f][0] * 0.25f, acc[f][1] * 0.25f);
            *(float2*)(plane + (t0 + 8) * 48 + s0) = make_float2(acc[f][2] * 0.25f, acc[f][3] * 0.25f);
        }
    }
    __syncthreads();

    // ---- P4: causal softmax, warp per row; repack fp16 in place ----
    for (int r = wid; r < NHc * Tc; r += 8) {
        int h = r / Tc, t = r - h * Tc;
        float* pf = (float*)(sm + AT_R) + h * 2304 + t * 48;
        int u1 = lane, u2 = lane + 32;
        bool v1 = (u1 <= t), v2 = (u2 < 48) && (u2 <= t);
        float f1 = v1 ? pf[u1] : -3.0e38f;
        float f2 = v2 ? pf[u2] : -3.0e38f;
        float m = fmaxf(f1, f2);
        #pragma unroll
        for (int o = 16; o; o >>= 1) m = fmaxf(m, __shfl_xor_sync(0xffffffffu, m, o));
        float e1 = v1 ? __expf(f1 - m) : 0.f;
        float e2 = v2 ? __expf(f2 - m) : 0.f;
        float s = e1 + e2;
        #pragma unroll
        for (int o = 16; o; o >>= 1) s += __shfl_xor_sync(0xffffffffu, s, o);
        float inv = 1.f / s;
        __half* ph = (__half*)pf;             // row base; fp16 probs occupy first 96 B
        ph[u1] = __float2half_rn(e1 * inv);
        if (u2 < 48) ph[u2] = __float2half_rn(e2 * inv);
    }
    __syncthreads();

    // ---- P5: x = p @ v -> fp16 into U1 (q dead) ----
    for (int u = wid; u < 24; u += 8) {
        int h = u / 3, mb = u % 3;
        float acc0[4] = {}, acc1[4] = {};
        uint32_t abase = sb + AT_R + h * 9216 + (mb * 16 + (lane & 15)) * 192 + ((lane >> 4) * 8) * 2;
        uint32_t bbase = sb + AT_V + ((lane & 7) + ((lane >> 3) & 1) * 8) * 272
                         + (h * 16 + ((lane >> 4) & 1) * 8) * 2;
        #pragma unroll
        for (int ks = 0; ks < 3; ks++) {
            uint32_t a[4], b[4];
            ldsm_x4(a, abase + ks * 32);
            ldsm_x4_trans(b, bbase + ks * 16 * 272);
            mma16816(acc0, a, b);
            mma16816(acc1, a, b + 2);
        }
        int t0 = mb * 16 + (lane >> 2);
        int c0 = h * 16 + (lane & 3) * 2;
        *(__half2*)(sm + AT_U1 + t0 * 272 + c0 * 2)       = __floats2half2_rn(acc0[0], acc0[1]);
        *(__half2*)(sm + AT_U1 + (t0 + 8) * 272 + c0 * 2) = __floats2half2_rn(acc0[2], acc0[3]);
        *(__half2*)(sm + AT_U1 + t0 * 272 + (c0 + 8) * 2)       = __floats2half2_rn(acc1[0], acc1[1]);
        *(__half2*)(sm + AT_U1 + (t0 + 8) * 272 + (c0 + 8) * 2) = __floats2half2_rn(acc1[2], acc1[3]);
    }
    __syncthreads();

    // ---- P6: stage ow (overwrites R) ----
    {
        const uint4* src = (const uint4*)owt;
        #pragma unroll 2
        for (int c = tid; c < 2048; c += 256) {
            int r = c >> 4, o = c & 15;
            *(uint4*)(sm + AT_R + r * 272 + o * 16) = src[c];
        }
    }
    __syncthreads();

    // ---- P7: out = x @ ow + ob -> global fp32 ----
    {
        float* op = out + bn * TDc;
        for (int u = wid; u < 24; u += 8) {
            int mb = u >> 3, n0 = (u & 7) * 16;
            float acc[2][4] = {};
            uint32_t aaddr = sb + AT_U1 + (mb * 16 + (lane & 15)) * 272 + ((lane >> 4) * 8) * 2;
            uint32_t baddr = sb + AT_R + (n0 + ((lane >> 4) << 3) + (lane & 7)) * 272
                             + (((lane >> 3) & 1) * 8) * 2;
            #pragma unroll
            for (int ks = 0; ks < 8; ks++) {
                uint32_t a[4], b[4];
                ldsm_x4(a, aaddr + ks * 32);
                ldsm_x4(b, baddr + ks * 32);
                mma16816(acc[0], a, b);
                mma16816(acc[1], a, b + 2);
            }
            int t0 = mb * 16 + (lane >> 2);
            #pragma unroll
            for (int f = 0; f < 2; f++) {
                int col = n0 + f * 8 + (lane & 3) * 2;
                float2 bb = *(const float2*)(sBias + 128 + col);
                *(float2*)(op + t0 * 128 + col) = make_float2(acc[f][0] + bb.x, acc[f][1] + bb.y);
                *(float2*)(op + (t0 + 8) * 128 + col) = make_float2(acc[f][2] + bb.x, acc[f][3] + bb.y);
            }
        }
    }
}

// ===========================================================================
extern "C" void kernel_launch(void* const* d_in, const int* in_sizes, int n_in,
                              void* d_out, int out_size)
{
    (void)in_sizes; (void)n_in; (void)out_size;
    const float* query = (const float*)d_in[0];
    const float* key_t = (const float*)d_in[1];
    const float* value = (const float*)d_in[2];
    const float* qw = (const float*)d_in[4];
    const float* qb = (const float*)d_in[5];
    const float* kw = (const float*)d_in[6];
    const float* kb = (const float*)d_in[7];
    const float* vw = (const float*)d_in[8];
    const float* vb = (const float*)d_in[9];
    const float* ow = (const float*)d_in[10];
    const float* ob = (const float*)d_in[11];
    float* out = (float*)d_out;

    __half *wtq, *wtk, *vwt, *owt, *gq, *gk;
    cudaGetSymbolAddress((void**)&wtq, g_wtq);
    cudaGetSymbolAddress((void**)&wtk, g_wtk);
    cudaGetSymbolAddress((void**)&vwt, g_vwt);
    cudaGetSymbolAddress((void**)&owt, g_owt);
    cudaGetSymbolAddress((void**)&gq,  g_q);
    cudaGetSymbolAddress((void**)&gk,  g_k);

    cudaFuncSetAttribute(conv_mma_kernel<0>, cudaFuncAttributeMaxDynamicSharedMemorySize, CV_SM);
    cudaFuncSetAttribute(conv_mma_kernel<1>, cudaFuncAttributeMaxDynamicSharedMemorySize, CV_SM);
    cudaFuncSetAttribute(attn_mma_kernel,    cudaFuncAttributeMaxDynamicSharedMemorySize, AT_SMEM);

    prep_w_kernel<<<192, 256>>>(qw, wtq);
    prep_w_kernel<<<192, 256>>>(kw, wtk);
    prep_proj_kernel<<<64, 256>>>(vw, vwt);
    prep_proj_kernel<<<64, 256>>>(ow, owt);
    conv_mma_kernel<0><<<BNc * 2, 256, CV_SM>>>(query, wtq, qb, gq);
    conv_mma_kernel<1><<<BNc * 2, 256, CV_SM>>>(key_t, wtk, kb, gk);
    attn_mma_kernel<<<BNc, 256, AT_SMEM>>>(value, vwt, vb, owt, ob, out);
}

// round 5
// speedup vs baseline: 3.5473x; 1.4646x over previous
#include <cuda_runtime.h>
#include <cuda_fp16.h>
#include <cstdint>

// Problem constants
constexpr int Bc = 8;
constexpr int Nc = 512;
constexpr int Tc = 48;
constexpr int Dc = 128;
constexpr int NHc = 8;
constexpr int BNc = Bc * Nc;         // 4096 tiles
constexpr int TDc = Tc * Dc;         // 6144 elems per (b,n) tile

// Scratch: fp16 conv outputs + pre-transposed fp16 weights
__device__ __half g_q[(size_t)BNc * TDc];
__device__ __half g_k[(size_t)BNc * TDc];
__device__ __half g_wtq[128 * 384];   // conv Wt[dout][k], k=j*128+din
__device__ __half g_wtk[128 * 384];
__device__ __half g_vwt[128 * 128];   // proj Wt[n][k] = w[k][n]
__device__ __half g_owt[128 * 128];

__device__ __forceinline__ uint32_t smem_u32(const void* p) {
    uint32_t a;
    asm("{ .reg .u64 t; cvta.to.shared.u64 t, %1; cvt.u32.u64 %0, t; }" : "=r"(a) : "l"(p));
    return a;
}
__device__ __forceinline__ void ldsm_x4(uint32_t* r, uint32_t a) {
    asm volatile("ldmatrix.sync.aligned.m8n8.x4.shared.b16 {%0,%1,%2,%3}, [%4];"
                 : "=r"(r[0]), "=r"(r[1]), "=r"(r[2]), "=r"(r[3]) : "r"(a));
}
__device__ __forceinline__ void ldsm_x4_trans(uint32_t* r, uint32_t a) {
    asm volatile("ldmatrix.sync.aligned.m8n8.x4.trans.shared.b16 {%0,%1,%2,%3}, [%4];"
                 : "=r"(r[0]), "=r"(r[1]), "=r"(r[2]), "=r"(r[3]) : "r"(a));
}
__device__ __forceinline__ void mma16816(float* c, const uint32_t* a, const uint32_t* b) {
    asm volatile("mma.sync.aligned.m16n8k16.row.col.f32.f16.f16.f32 "
                 "{%0,%1,%2,%3}, {%4,%5,%6,%7}, {%8,%9}, {%0,%1,%2,%3};"
                 : "+f"(c[0]), "+f"(c[1]), "+f"(c[2]), "+f"(c[3])
                 : "r"(a[0]), "r"(a[1]), "r"(a[2]), "r"(a[3]), "r"(b[0]), "r"(b[1]));
}
__device__ __forceinline__ uint32_t pack_h2(float a, float b) {
    __half2 h = __floats2half2_rn(a, b);
    return *reinterpret_cast<uint32_t*>(&h);
}
__device__ __forceinline__ int seg_of(int t) { return (t < 12) ? 0 : ((t < 24) ? 1 : 2); }

// ===========================================================================
// Fused weight prep (single launch)
// ===========================================================================
__global__ void prep_all_kernel(const float* __restrict__ qw, const float* __restrict__ kw,
                                const float* __restrict__ vw, const float* __restrict__ ow)
{
    int i = blockIdx.x * blockDim.x + threadIdx.x;
    if (i < 98304) {            // conv weights: Wt[dout][j*128+din] = w[j][din][dout]
        const float* w = (i < 49152) ? qw : kw;
        __half* out    = (i < 49152) ? g_wtq : g_wtk;
        int l = (i < 49152) ? i : i - 49152;
        int dout = l / 384, k = l % 384;
        int j = k >> 7, din = k & 127;
        out[l] = __float2half(w[(j * 128 + din) * 128 + dout]);
    } else if (i < 131072) {    // proj weights: Wt[n][k] = w[k][n]
        int l = i - 98304;
        const float* w = (l < 16384) ? vw : ow;
        __half* out    = (l < 16384) ? g_vwt : g_owt;
        int m = l & 16383;
        int n = m >> 7, k = m & 127;
        out[m] = __float2half(w[k * 128 + n]);
    }
}

// ===========================================================================
// Persistent conv kernel (both convs in one launch, grid = 2048, 384 thr).
// blockIdx: conv = bx>>10 (0=q OFFB0, 1=k OFFB1); idx=bx&1023: half=idx&1,
// group=idx>>1. Each CTA stages its 64-row weight half once, then loops over
// 8 tiles: fill X (always-store segment-padded im2col), sync, 12-warp MMA.
// smem: X 48x784 + W 64x784 = 87808 B => 2 CTAs/SM.
// ===========================================================================
constexpr int CXS   = 784;
constexpr int CV_X  = 0;
constexpr int CV_W  = 37632;
constexpr int CV_SM = 87808;

__global__ __launch_bounds__(384, 2)
void conv_mma_kernel(const float* __restrict__ query, const float* __restrict__ key_t,
                     const float* __restrict__ qb, const float* __restrict__ kb)
{
    extern __shared__ char sm[];
    const uint32_t sb = smem_u32(sm);
    const int tid = threadIdx.x, wid = tid >> 5, lane = tid & 31;
    const int conv  = blockIdx.x >> 10;
    const int idx   = blockIdx.x & 1023;
    const int half  = idx & 1;
    const int group = idx >> 1;
    const int nb    = half * 64;
    const int offb  = conv;                       // q:0, k:1

    const float*  in   = conv ? key_t : query;
    const __half* wt   = conv ? g_wtk : g_wtq;
    const float*  bias = conv ? kb : qb;
    __half*       outb = conv ? g_k : g_q;

    // Stage this CTA's 64 weight rows once
    #pragma unroll 2
    for (int c = tid; c < 64 * 48; c += 384) {
        int n = c / 48, ch = c % 48;
        uint4 v = *(const uint4*)((const char*)wt + (nb + n) * 768 + ch * 16);
        *(uint4*)(sm + CV_W + n * CXS + ch * 16) = v;
    }

    for (int it = 0; it < 8; it++) {
        const int tile = group + 512 * it;
        // Fill X (always-store: zero or converted value)
        {
            const float* inp = in + (size_t)tile * TDc;
            #pragma unroll 2
            for (int i = tid; i < 48 * 192; i += 384) {
                int t = i / 192, p = i - t * 192;
                int j = p >> 6, dp = p & 63;
                int sg = seg_of(t);
                int s0 = (sg == 0) ? 0 : (sg == 1 ? 12 : 24);
                int e0 = (sg == 0) ? 12 : (sg == 1 ? 24 : 48);
                int src = t + j - (2 - offb);
                __half2 h = __floats2half2_rn(0.f, 0.f);
                if (src >= s0 && src < e0) {
                    float2 v = *(const float2*)(inp + src * 128 + dp * 2);
                    h = __floats2half2_rn(v.x, v.y);
                }
                *(__half2*)(sm + CV_X + t * CXS + (j * 128 + dp * 2) * 2) = h;
            }
        }
        __syncthreads();

        // 12 warps = 12 m16n16 units (mb = wid/4, nc = wid%4)
        {
            const int mb = wid >> 2, nc = wid & 3;
            float acc[2][4] = {};
            uint32_t aaddr = sb + CV_X + (mb * 16 + (lane & 15)) * CXS + ((lane >> 4) * 8) * 2;
            uint32_t baddr = sb + CV_W + (nc * 16 + ((lane >> 4) << 3) + (lane & 7)) * CXS
                             + (((lane >> 3) & 1) * 8) * 2;
            #pragma unroll 4
            for (int ks = 0; ks < 24; ks++) {
                uint32_t a[4], b[4];
                ldsm_x4(a, aaddr + ks * 32);
                ldsm_x4(b, baddr + ks * 32);
                mma16816(acc[0], a, b);
                mma16816(acc[1], a, b + 2);
            }
            int t0 = mb * 16 + (lane >> 2);
            __half* op = outb + (size_t)tile * TDc;
            #pragma unroll
            for (int f = 0; f < 2; f++) {
                int col = nb + nc * 16 + f * 8 + (lane & 3) * 2;
                float2 bb = *(const float2*)(bias + col);
                *(__half2*)(op + t0 * 128 + col) =
                    __floats2half2_rn(acc[f][0] + bb.x, acc[f][1] + bb.y);
                *(__half2*)(op + (t0 + 8) * 128 + col) =
                    __floats2half2_rn(acc[f][2] + bb.x, acc[f][3] + bb.y);
            }
        }
        __syncthreads();
    }
}

// ===========================================================================
// Flash-style attention kernel, one CTA per (b,n), 73.2 KB smem => 3 CTAs/SM.
// Regions (fp16 tiles, row stride 272 B):
//   U1 [0,13056):     value -> q -> x  (time-aliased)
//   K  [13056,26112): k tile
//   V  [26112,39168): projected v
//   R  [39168,73984): vw -> ow (time-aliased, 128 rows)
//   BIAS [73984,75008): vb(128)+ob(128) fp32
// Scores/softmax/probs live entirely in registers (C-frag == A-frag trick).
// ===========================================================================
constexpr int AT_U1   = 0;
constexpr int AT_K    = 13056;
constexpr int AT_V    = 26112;
constexpr int AT_R    = 39168;
constexpr int AT_BIAS = AT_R + 128 * 272;   // 73984
constexpr int AT_SMEM = AT_BIAS + 1024;     // 75008

__global__ __launch_bounds__(256, 3)
void attn_mma_kernel(const float* __restrict__ value,
                     const float* __restrict__ vb, const float* __restrict__ ob,
                     float* __restrict__ out)
{
    extern __shared__ char sm[];
    const uint32_t sb = smem_u32(sm);
    const int tid = threadIdx.x, wid = tid >> 5, lane = tid & 31;
    const size_t bn = blockIdx.x;
    float* sBias = (float*)(sm + AT_BIAS);

    // ---- P0: biases, vw -> R, value(fp32->fp16) -> U1, k -> K ----
    sBias[tid] = (tid < 128) ? vb[tid] : ob[tid - 128];
    {
        const uint4* src = (const uint4*)g_vwt;
        #pragma unroll 2
        for (int c = tid; c < 2048; c += 256) {
            int r = c >> 4, o = c & 15;
            *(uint4*)(sm + AT_R + r * 272 + o * 16) = src[c];
        }
    }
    {
        const float2* src = (const float2*)(value + bn * TDc);
        #pragma unroll 2
        for (int i = tid; i < 3072; i += 256) {
            int r = i >> 6, c = i & 63;
            float2 v = src[i];
            *(__half2*)(sm + AT_U1 + r * 272 + c * 4) = __floats2half2_rn(v.x, v.y);
        }
    }
    {
        const uint4* src = (const uint4*)(g_k + bn * TDc);
        for (int c = tid; c < 768; c += 256) {
            int r = c >> 4, o = c & 15;
            *(uint4*)(sm + AT_K + r * 272 + o * 16) = src[c];
        }
    }
    __syncthreads();

    // ---- P1: v = value @ vw + vb -> V ----
    for (int u = wid; u < 24; u += 8) {
        int mb = u >> 3, n0 = (u & 7) * 16;
        float acc[2][4] = {};
        uint32_t aaddr = sb + AT_U1 + (mb * 16 + (lane & 15)) * 272 + ((lane >> 4) * 8) * 2;
        uint32_t baddr = sb + AT_R + (n0 + ((lane >> 4) << 3) + (lane & 7)) * 272
                         + (((lane >> 3) & 1) * 8) * 2;
        #pragma unroll
        for (int ks = 0; ks < 8; ks++) {
            uint32_t a[4], b[4];
            ldsm_x4(a, aaddr + ks * 32);
            ldsm_x4(b, baddr + ks * 32);
            mma16816(acc[0], a, b);
            mma16816(acc[1], a, b + 2);
        }
        int t0 = mb * 16 + (lane >> 2);
        #pragma unroll
        for (int f = 0; f < 2; f++) {
            int col = n0 + f * 8 + (lane & 3) * 2;
            float2 bb = *(const float2*)(sBias + col);
            *(__half2*)(sm + AT_V + t0 * 272 + col * 2) =
                __floats2half2_rn(acc[f][0] + bb.x, acc[f][1] + bb.y);
            *(__half2*)(sm + AT_V + (t0 + 8) * 272 + col * 2) =
                __floats2half2_rn(acc[f][2] + bb.x, acc[f][3] + bb.y);
        }
    }
    __syncthreads();

    // ---- P2: stage q -> U1 (value dead) and ow -> R (vw dead) ----
    {
        const uint4* src = (const uint4*)(g_q + bn * TDc);
        for (int c = tid; c < 768; c += 256) {
            int r = c >> 4, o = c & 15;
            *(uint4*)(sm + AT_U1 + r * 272 + o * 16) = src[c];
        }
    }
    {
        const uint4* src = (const uint4*)g_owt;
        #pragma unroll 2
        for (int c = tid; c < 2048; c += 256) {
            int r = c >> 4, o = c & 15;
            *(uint4*)(sm + AT_R + r * 272 + o * 16) = src[c];
        }
    }
    __syncthreads();

    // ---- P3-5 fused: scores -> register softmax -> P@V, per warp-unit ----
    for (int u = wid; u < 24; u += 8) {
        int h = u / 3, mb = u - (u / 3) * 3;
        // scores = q_h @ k_h^T (fp32 frags)
        float acc[6][4] = {};
        {
            uint32_t a[4];
            ldsm_x4(a, sb + AT_U1 + (mb * 16 + (lane & 15)) * 272
                       + (h * 16 + (lane >> 4) * 8) * 2);
            #pragma unroll
            for (int np = 0; np < 3; np++) {
                uint32_t b[4];
                ldsm_x4(b, sb + AT_K + (np * 16 + ((lane >> 4) << 3) + (lane & 7)) * 272
                           + (h * 16 + ((lane >> 3) & 1) * 8) * 2);
                mma16816(acc[np * 2], a, b);
                mma16816(acc[np * 2 + 1], a, b + 2);
            }
        }
        // scale + causal mask in registers
        const int r0 = mb * 16 + (lane >> 2);
        #pragma unroll
        for (int f = 0; f < 6; f++) {
            int cb = (f >> 1) * 16 + (f & 1) * 8 + (lane & 3) * 2;
            #pragma unroll
            for (int jj = 0; jj < 4; jj++) {
                int row = r0 + ((jj >> 1) << 3);
                int col = cb + (jj & 1);
                acc[f][jj] = (col <= row) ? acc[f][jj] * 0.25f : -1e30f;
            }
        }
        // register softmax (rows r0 and r0+8); 4-lane shfl across lane&3
        float m0 = -1e30f, m1 = -1e30f;
        #pragma unroll
        for (int f = 0; f < 6; f++) {
            m0 = fmaxf(m0, fmaxf(acc[f][0], acc[f][1]));
            m1 = fmaxf(m1, fmaxf(acc[f][2], acc[f][3]));
        }
        m0 = fmaxf(m0, __shfl_xor_sync(0xffffffffu, m0, 1));
        m0 = fmaxf(m0, __shfl_xor_sync(0xffffffffu, m0, 2));
        m1 = fmaxf(m1, __shfl_xor_sync(0xffffffffu, m1, 1));
        m1 = fmaxf(m1, __shfl_xor_sync(0xffffffffu, m1, 2));
        float s0 = 0.f, s1 = 0.f;
        #pragma unroll
        for (int f = 0; f < 6; f++) {
            acc[f][0] = __expf(acc[f][0] - m0); s0 += acc[f][0];
            acc[f][1] = __expf(acc[f][1] - m0); s0 += acc[f][1];
            acc[f][2] = __expf(acc[f][2] - m1); s1 += acc[f][2];
            acc[f][3] = __expf(acc[f][3] - m1); s1 += acc[f][3];
        }
        s0 += __shfl_xor_sync(0xffffffffu, s0, 1);
        s0 += __shfl_xor_sync(0xffffffffu, s0, 2);
        s1 += __shfl_xor_sync(0xffffffffu, s1, 1);
        s1 += __shfl_xor_sync(0xffffffffu, s1, 2);
        float i0 = 1.f / s0, i1 = 1.f / s1;
        // pack probs: C-frag layout == A-frag layout per 16-wide k-step
        uint32_t pa[3][4];
        #pragma unroll
        for (int ks = 0; ks < 3; ks++) {
            pa[ks][0] = pack_h2(acc[2 * ks][0] * i0,     acc[2 * ks][1] * i0);
            pa[ks][1] = pack_h2(acc[2 * ks][2] * i1,     acc[2 * ks][3] * i1);
            pa[ks][2] = pack_h2(acc[2 * ks + 1][0] * i0, acc[2 * ks + 1][1] * i0);
            pa[ks][3] = pack_h2(acc[2 * ks + 1][2] * i1, acc[2 * ks + 1][3] * i1);
        }
        // x = p @ v_h -> overwrite own q block in U1
        float x0[4] = {}, x1[4] = {};
        uint32_t bbase = sb + AT_V + ((lane & 7) + ((lane >> 3) & 1) * 8) * 272
                         + (h * 16 + ((lane >> 4) & 1) * 8) * 2;
        #pragma unroll
        for (int ks = 0; ks < 3; ks++) {
            uint32_t b[4];
            ldsm_x4_trans(b, bbase + ks * 16 * 272);
            mma16816(x0, pa[ks], b);
            mma16816(x1, pa[ks], b + 2);
        }
        int c0 = h * 16 + (lane & 3) * 2;
        *(__half2*)(sm + AT_U1 + r0 * 272 + c0 * 2)             = __floats2half2_rn(x0[0], x0[1]);
        *(__half2*)(sm + AT_U1 + (r0 + 8) * 272 + c0 * 2)       = __floats2half2_rn(x0[2], x0[3]);
        *(__half2*)(sm + AT_U1 + r0 * 272 + (c0 + 8) * 2)       = __floats2half2_rn(x1[0], x1[1]);
        *(__half2*)(sm + AT_U1 + (r0 + 8) * 272 + (c0 + 8) * 2) = __floats2half2_rn(x1[2], x1[3]);
    }
    __syncthreads();

    // ---- P7: out = x @ ow + ob -> global fp32 ----
    {
        float* op = out + bn * TDc;
        for (int u = wid; u < 24; u += 8) {
            int mb = u >> 3, n0 = (u & 7) * 16;
            float acc[2][4] = {};
            uint32_t aaddr = sb + AT_U1 + (mb * 16 + (lane & 15)) * 272 + ((lane >> 4) * 8) * 2;
            uint32_t baddr = sb + AT_R + (n0 + ((lane >> 4) << 3) + (lane & 7)) * 272
                             + (((lane >> 3) & 1) * 8) * 2;
            #pragma unroll
            for (int ks = 0; ks < 8; ks++) {
                uint32_t a[4], b[4];
                ldsm_x4(a, aaddr + ks * 32);
                ldsm_x4(b, baddr + ks * 32);
                mma16816(acc[0], a, b);
                mma16816(acc[1], a, b + 2);
            }
            int t0 = mb * 16 + (lane >> 2);
            #pragma unroll
            for (int f = 0; f < 2; f++) {
                int col = n0 + f * 8 + (lane & 3) * 2;
                float2 bb = *(const float2*)(sBias + 128 + col);
                *(float2*)(op + t0 * 128 + col) = make_float2(acc[f][0] + bb.x, acc[f][1] + bb.y);
                *(float2*)(op + (t0 + 8) * 128 + col) = make_float2(acc[f][2] + bb.x, acc[f][3] + bb.y);
            }
        }
    }
}

// ===========================================================================
extern "C" void kernel_launch(void* const* d_in, const int* in_sizes, int n_in,
                              void* d_out, int out_size)
{
    (void)in_sizes; (void)n_in; (void)out_size;
    const float* query = (const float*)d_in[0];
    const float* key_t = (const float*)d_in[1];
    const float* value = (const float*)d_in[2];
    const float* qw = (const float*)d_in[4];
    const float* qb = (const float*)d_in[5];
    const float* kw = (const float*)d_in[6];
    const float* kb = (const float*)d_in[7];
    const float* vw = (const float*)d_in[8];
    const float* vb = (const float*)d_in[9];
    const float* ow = (const float*)d_in[10];
    const float* ob = (const float*)d_in[11];
    float* out = (float*)d_out;

    cudaFuncSetAttribute(conv_mma_kernel, cudaFuncAttributeMaxDynamicSharedMemorySize, CV_SM);
    cudaFuncSetAttribute(attn_mma_kernel, cudaFuncAttributeMaxDynamicSharedMemorySize, AT_SMEM);

    prep_all_kernel<<<512, 256>>>(qw, kw, vw, ow);
    conv_mma_kernel<<<2048, 384, CV_SM>>>(query, key_t, qb, kb);
    attn_mma_kernel<<<BNc, 256, AT_SMEM>>>(value, vb, ob, out);
}

// round 6
// speedup vs baseline: 5.6634x; 1.5966x over previous
#include <cuda_runtime.h>
#include <cuda_fp16.h>
#include <cstdint>

// Problem constants
constexpr int Bc = 8;
constexpr int Nc = 512;
constexpr int Tc = 48;
constexpr int Dc = 128;
constexpr int BNc = Bc * Nc;         // 4096 tiles
constexpr int TDc = Tc * Dc;         // 6144 elems per (b,n) tile

// Scratch: fp16 GEMM outputs + pre-transposed fp16 weights
__device__ __half g_q[(size_t)BNc * TDc];
__device__ __half g_k[(size_t)BNc * TDc];
__device__ __half g_v[(size_t)BNc * TDc];
__device__ __half g_wtq[128 * 384];   // conv Wt[dout][k], k=j*128+din
__device__ __half g_wtk[128 * 384];
__device__ __half g_vwt[128 * 128];   // proj Wt[n][k] = w[k][n]
__device__ __half g_owt[128 * 128];

__device__ __forceinline__ uint32_t smem_u32(const void* p) {
    uint32_t a;
    asm("{ .reg .u64 t; cvta.to.shared.u64 t, %1; cvt.u32.u64 %0, t; }" : "=r"(a) : "l"(p));
    return a;
}
__device__ __forceinline__ void ldsm_x4(uint32_t* r, uint32_t a) {
    asm volatile("ldmatrix.sync.aligned.m8n8.x4.shared.b16 {%0,%1,%2,%3}, [%4];"
                 : "=r"(r[0]), "=r"(r[1]), "=r"(r[2]), "=r"(r[3]) : "r"(a));
}
__device__ __forceinline__ void ldsm_x4_trans(uint32_t* r, uint32_t a) {
    asm volatile("ldmatrix.sync.aligned.m8n8.x4.trans.shared.b16 {%0,%1,%2,%3}, [%4];"
                 : "=r"(r[0]), "=r"(r[1]), "=r"(r[2]), "=r"(r[3]) : "r"(a));
}
__device__ __forceinline__ void mma16816(float* c, const uint32_t* a, const uint32_t* b) {
    asm volatile("mma.sync.aligned.m16n8k16.row.col.f32.f16.f16.f32 "
                 "{%0,%1,%2,%3}, {%4,%5,%6,%7}, {%8,%9}, {%0,%1,%2,%3};"
                 : "+f"(c[0]), "+f"(c[1]), "+f"(c[2]), "+f"(c[3])
                 : "r"(a[0]), "r"(a[1]), "r"(a[2]), "r"(a[3]), "r"(b[0]), "r"(b[1]));
}
__device__ __forceinline__ uint32_t pack_h2(float a, float b) {
    __half2 h = __floats2half2_rn(a, b);
    return *reinterpret_cast<uint32_t*>(&h);
}
__device__ __forceinline__ int seg_of(int t) { return (t < 12) ? 0 : ((t < 24) ? 1 : 2); }

// ===========================================================================
// Fused weight prep (single launch)
// ===========================================================================
__global__ void prep_all_kernel(const float* __restrict__ qw, const float* __restrict__ kw,
                                const float* __restrict__ vw, const float* __restrict__ ow)
{
    int i = blockIdx.x * blockDim.x + threadIdx.x;
    if (i < 98304) {            // conv weights: Wt[dout][j*128+din] = w[j][din][dout]
        const float* w = (i < 49152) ? qw : kw;
        __half* out    = (i < 49152) ? g_wtq : g_wtk;
        int l = (i < 49152) ? i : i - 49152;
        int dout = l / 384, k = l % 384;
        int j = k >> 7, din = k & 127;
        out[l] = __float2half(w[(j * 128 + din) * 128 + dout]);
    } else if (i < 131072) {    // proj weights: Wt[n][k] = w[k][n]
        int l = i - 98304;
        const float* w = (l < 16384) ? vw : ow;
        __half* out    = (l < 16384) ? g_vwt : g_owt;
        int m = l & 16383;
        int n = m >> 7, k = m & 127;
        out[m] = __float2half(w[k * 128 + n]);
    }
}

// ===========================================================================
// Persistent GEMM kernel: q-conv (K=384), k-conv (K=384), v-proj (K=128).
// grid = 1536: kind = bx>>9 (0=q,1=k,2=v); half = bx&1 (64 output cols);
// group = (bx&511)>>1; tiles = group + 256*it, it in [0,16).
// Input staged once per tile in 60-row zero-padded layout (row = t+2+4*seg),
// stride 272 B. Conv A-views synthesized via per-lane ldmatrix row addresses:
// row = t + 4*seg(t) + j + kind (q:+j, k:+j+1); v uses identity row t+2+4seg.
// Weights (64 rows of this CTA's half) staged once per CTA.
// smem: IN 64x272 + W 64x784 + bias = 68 KB => 3 CTAs/SM.
// ===========================================================================
constexpr int GV_IN   = 0;                  // 64*272 = 17408
constexpr int GV_W    = 17408;              // up to 64*784 = 50176
constexpr int GV_BIAS = 17408 + 50176;      // 67584, 64 floats
constexpr int GV_SM   = 67584 + 512;        // 68096

__constant__ unsigned char c_padrows[12] = {0, 1, 14, 15, 16, 17, 30, 31, 32, 33, 58, 59};

__global__ __launch_bounds__(384, 3)
void gemm3_kernel(const float* __restrict__ query, const float* __restrict__ key_t,
                  const float* __restrict__ value,
                  const float* __restrict__ qb, const float* __restrict__ kb,
                  const float* __restrict__ vb)
{
    extern __shared__ char sm[];
    const uint32_t sb = smem_u32(sm);
    const int tid = threadIdx.x, wid = tid >> 5, lane = tid & 31;
    const int kind  = blockIdx.x >> 9;            // 0 q, 1 k, 2 v
    const int rr    = blockIdx.x & 511;
    const int half  = rr & 1;
    const int group = rr >> 1;                    // 0..255
    const int nb    = half * 64;

    const float*  in   = (kind == 0) ? query : (kind == 1) ? key_t : value;
    const __half* wt   = (kind == 0) ? g_wtq : (kind == 1) ? g_wtk : g_vwt;
    const float*  bias = (kind == 0) ? qb : (kind == 1) ? kb : vb;
    __half*       outb = (kind == 0) ? g_q : (kind == 1) ? g_k : g_v;
    const int wrow16   = (kind == 2) ? 16 : 48;   // uint4 chunks per weight row
    const int wstride  = (kind == 2) ? 272 : 784;

    // One-time staging: weights (64 rows of this half), bias, zero pad rows
    for (int c = tid; c < 64 * wrow16; c += 384) {
        int n = c / wrow16, ch = c - n * wrow16;
        uint4 v = *(const uint4*)((const char*)wt + ((nb + n) * wrow16 + ch) * 16);
        *(uint4*)(sm + GV_W + n * wstride + ch * 16) = v;
    }
    if (tid < 16) ((float4*)(sm + GV_BIAS))[tid] = ((const float4*)(bias + nb))[tid];
    if (tid < 204) {     // 12 pad rows x 17 uint4
        int pr = c_padrows[tid / 17], ch = tid % 17;
        *(uint4*)(sm + GV_IN + pr * 272 + ch * 16) = make_uint4(0, 0, 0, 0);
    }

    // Per-warp constants
    const int mb = wid >> 2, nc = wid & 3;
    const int t_l = mb * 16 + (lane & 15);
    const int p_t = t_l + 4 * seg_of(t_l);        // padded row - 2
    const uint32_t acol  = ((lane >> 4) * 8) * 2;
    const uint32_t brow  = nc * 16 + ((lane >> 4) << 3) + (lane & 7);
    const uint32_t bcol0 = ((lane >> 3) & 1) * 16;
    const uint32_t baddr_base = sb + GV_W + brow * wstride + bcol0;
    const int t0 = mb * 16 + (lane >> 2);

    for (int it = 0; it < 16; it++) {
        const int tile = group + 256 * it;
        __syncthreads();   // prev MMA reads done before refill
        // Fill 48 data rows (fp32 -> fp16), padded layout
        {
            const float* inp = in + (size_t)tile * TDc;
            #pragma unroll
            for (int i = tid; i < 3072; i += 384) {
                int r = i >> 6, c = i & 63;
                float2 v = *(const float2*)(inp + r * 128 + c * 2);
                *(__half2*)(sm + GV_IN + (r + 2 + 4 * seg_of(r)) * 272 + c * 4) =
                    __floats2half2_rn(v.x, v.y);
            }
        }
        __syncthreads();

        float acc[2][4] = {};
        if (kind < 2) {
            #pragma unroll
            for (int j = 0; j < 3; j++) {
                const uint32_t aaddr = sb + GV_IN + (p_t + j + kind) * 272 + acol;
                const uint32_t baddr = baddr_base + j * 256;
                #pragma unroll
                for (int kk = 0; kk < 8; kk++) {
                    uint32_t a[4], b[4];
                    ldsm_x4(a, aaddr + kk * 32);
                    ldsm_x4(b, baddr + kk * 32);
                    mma16816(acc[0], a, b);
                    mma16816(acc[1], a, b + 2);
                }
            }
        } else {
            const uint32_t aaddr = sb + GV_IN + (p_t + 2) * 272 + acol;
            #pragma unroll
            for (int kk = 0; kk < 8; kk++) {
                uint32_t a[4], b[4];
                ldsm_x4(a, aaddr + kk * 32);
                ldsm_x4(b, baddr_base + kk * 32);
                mma16816(acc[0], a, b);
                mma16816(acc[1], a, b + 2);
            }
        }

        // Epilogue: bias + fp16 store
        __half* op = outb + (size_t)tile * TDc;
        #pragma unroll
        for (int f = 0; f < 2; f++) {
            int cl = nc * 16 + f * 8 + (lane & 3) * 2;
            float2 bb = *(const float2*)((const float*)(sm + GV_BIAS) + cl);
            *(__half2*)(op + t0 * 128 + nb + cl) =
                __floats2half2_rn(acc[f][0] + bb.x, acc[f][1] + bb.y);
            *(__half2*)(op + (t0 + 8) * 128 + nb + cl) =
                __floats2half2_rn(acc[f][2] + bb.x, acc[f][3] + bb.y);
        }
    }
}

// ===========================================================================
// Attention kernel, one CTA per (b,n), 72.75 KB smem => 3 CTAs/SM.
// Regions (fp16 tiles, row stride 272 B):
//   U1 [0,13056):     q -> x (time-aliased)
//   K  [13056,26112): k
//   V  [26112,39168): v (bias already applied by gemm3)
//   OW [39168,73984): o-proj weight
//   BIAS [73984,74496): ob fp32 (128)
// Scores/softmax/probs in registers (C-frag == A-frag). Two syncthreads.
// ===========================================================================
constexpr int AT_U1   = 0;
constexpr int AT_K    = 13056;
constexpr int AT_V    = 26112;
constexpr int AT_OW   = 39168;
constexpr int AT_BIAS = AT_OW + 128 * 272;  // 73984
constexpr int AT_SMEM = AT_BIAS + 512;      // 74496

__global__ __launch_bounds__(256, 3)
void attn_mma_kernel(const float* __restrict__ ob, float* __restrict__ out)
{
    extern __shared__ char sm[];
    const uint32_t sb = smem_u32(sm);
    const int tid = threadIdx.x, wid = tid >> 5, lane = tid & 31;
    const size_t bn = blockIdx.x;

    // ---- P0: stage q, k, v, ow, ob ----
    if (tid < 128) ((float*)(sm + AT_BIAS))[tid] = ob[tid];
    {
        const uint4* sq = (const uint4*)(g_q + bn * TDc);
        const uint4* sk = (const uint4*)(g_k + bn * TDc);
        const uint4* sv = (const uint4*)(g_v + bn * TDc);
        for (int c = tid; c < 768; c += 256) {
            int r = c >> 4, o = c & 15;
            *(uint4*)(sm + AT_U1 + r * 272 + o * 16) = sq[c];
            *(uint4*)(sm + AT_K  + r * 272 + o * 16) = sk[c];
            *(uint4*)(sm + AT_V  + r * 272 + o * 16) = sv[c];
        }
        const uint4* so = (const uint4*)g_owt;
        #pragma unroll 2
        for (int c = tid; c < 2048; c += 256) {
            int r = c >> 4, o = c & 15;
            *(uint4*)(sm + AT_OW + r * 272 + o * 16) = so[c];
        }
    }
    __syncthreads();

    // ---- P1 fused: scores -> register softmax -> P@V, per warp-unit ----
    for (int u = wid; u < 24; u += 8) {
        int h = u / 3, mb = u - (u / 3) * 3;
        float acc[6][4] = {};
        {
            uint32_t a[4];
            ldsm_x4(a, sb + AT_U1 + (mb * 16 + (lane & 15)) * 272
                       + (h * 16 + (lane >> 4) * 8) * 2);
            #pragma unroll
            for (int np = 0; np < 3; np++) {
                uint32_t b[4];
                ldsm_x4(b, sb + AT_K + (np * 16 + ((lane >> 4) << 3) + (lane & 7)) * 272
                           + (h * 16 + ((lane >> 3) & 1) * 8) * 2);
                mma16816(acc[np * 2], a, b);
                mma16816(acc[np * 2 + 1], a, b + 2);
            }
        }
        const int r0 = mb * 16 + (lane >> 2);
        #pragma unroll
        for (int f = 0; f < 6; f++) {
            int cb = (f >> 1) * 16 + (f & 1) * 8 + (lane & 3) * 2;
            #pragma unroll
            for (int jj = 0; jj < 4; jj++) {
                int row = r0 + ((jj >> 1) << 3);
                int col = cb + (jj & 1);
                acc[f][jj] = (col <= row) ? acc[f][jj] * 0.25f : -1e30f;
            }
        }
        float m0 = -1e30f, m1 = -1e30f;
        #pragma unroll
        for (int f = 0; f < 6; f++) {
            m0 = fmaxf(m0, fmaxf(acc[f][0], acc[f][1]));
            m1 = fmaxf(m1, fmaxf(acc[f][2], acc[f][3]));
        }
        m0 = fmaxf(m0, __shfl_xor_sync(0xffffffffu, m0, 1));
        m0 = fmaxf(m0, __shfl_xor_sync(0xffffffffu, m0, 2));
        m1 = fmaxf(m1, __shfl_xor_sync(0xffffffffu, m1, 1));
        m1 = fmaxf(m1, __shfl_xor_sync(0xffffffffu, m1, 2));
        float s0 = 0.f, s1 = 0.f;
        #pragma unroll
        for (int f = 0; f < 6; f++) {
            acc[f][0] = __expf(acc[f][0] - m0); s0 += acc[f][0];
            acc[f][1] = __expf(acc[f][1] - m0); s0 += acc[f][1];
            acc[f][2] = __expf(acc[f][2] - m1); s1 += acc[f][2];
            acc[f][3] = __expf(acc[f][3] - m1); s1 += acc[f][3];
        }
        s0 += __shfl_xor_sync(0xffffffffu, s0, 1);
        s0 += __shfl_xor_sync(0xffffffffu, s0, 2);
        s1 += __shfl_xor_sync(0xffffffffu, s1, 1);
        s1 += __shfl_xor_sync(0xffffffffu, s1, 2);
        float i0 = 1.f / s0, i1 = 1.f / s1;
        uint32_t pa[3][4];
        #pragma unroll
        for (int ks = 0; ks < 3; ks++) {
            pa[ks][0] = pack_h2(acc[2 * ks][0] * i0,     acc[2 * ks][1] * i0);
            pa[ks][1] = pack_h2(acc[2 * ks][2] * i1,     acc[2 * ks][3] * i1);
            pa[ks][2] = pack_h2(acc[2 * ks + 1][0] * i0, acc[2 * ks + 1][1] * i0);
            pa[ks][3] = pack_h2(acc[2 * ks + 1][2] * i1, acc[2 * ks + 1][3] * i1);
        }
        float x0[4] = {}, x1[4] = {};
        uint32_t bbase = sb + AT_V + ((lane & 7) + ((lane >> 3) & 1) * 8) * 272
                         + (h * 16 + ((lane >> 4) & 1) * 8) * 2;
        #pragma unroll
        for (int ks = 0; ks < 3; ks++) {
            uint32_t b[4];
            ldsm_x4_trans(b, bbase + ks * 16 * 272);
            mma16816(x0, pa[ks], b);
            mma16816(x1, pa[ks], b + 2);
        }
        int c0 = h * 16 + (lane & 3) * 2;
        *(__half2*)(sm + AT_U1 + r0 * 272 + c0 * 2)             = __floats2half2_rn(x0[0], x0[1]);
        *(__half2*)(sm + AT_U1 + (r0 + 8) * 272 + c0 * 2)       = __floats2half2_rn(x0[2], x0[3]);
        *(__half2*)(sm + AT_U1 + r0 * 272 + (c0 + 8) * 2)       = __floats2half2_rn(x1[0], x1[1]);
        *(__half2*)(sm + AT_U1 + (r0 + 8) * 272 + (c0 + 8) * 2) = __floats2half2_rn(x1[2], x1[3]);
    }
    __syncthreads();

    // ---- P2: out = x @ ow + ob -> global fp32 ----
    {
        float* op = out + bn * TDc;
        for (int u = wid; u < 24; u += 8) {
            int mb = u >> 3, n0 = (u & 7) * 16;
            float acc[2][4] = {};
            uint32_t aaddr = sb + AT_U1 + (mb * 16 + (lane & 15)) * 272 + ((lane >> 4) * 8) * 2;
            uint32_t baddr = sb + AT_OW + (n0 + ((lane >> 4) << 3) + (lane & 7)) * 272
                             + (((lane >> 3) & 1) * 8) * 2;
            #pragma unroll
            for (int ks = 0; ks < 8; ks++) {
                uint32_t a[4], b[4];
                ldsm_x4(a, aaddr + ks * 32);
                ldsm_x4(b, baddr + ks * 32);
                mma16816(acc[0], a, b);
                mma16816(acc[1], a, b + 2);
            }
            int t0 = mb * 16 + (lane >> 2);
            #pragma unroll
            for (int f = 0; f < 2; f++) {
                int col = n0 + f * 8 + (lane & 3) * 2;
                float2 bb = *(const float2*)((const float*)(sm + AT_BIAS) + col);
                *(float2*)(op + t0 * 128 + col) = make_float2(acc[f][0] + bb.x, acc[f][1] + bb.y);
                *(float2*)(op + (t0 + 8) * 128 + col) = make_float2(acc[f][2] + bb.x, acc[f][3] + bb.y);
            }
        }
    }
}

// ===========================================================================
extern "C" void kernel_launch(void* const* d_in, const int* in_sizes, int n_in,
                              void* d_out, int out_size)
{
    (void)in_sizes; (void)n_in; (void)out_size;
    const float* query = (const float*)d_in[0];
    const float* key_t = (const float*)d_in[1];
    const float* value = (const float*)d_in[2];
    const float* qw = (const float*)d_in[4];
    const float* qb = (const float*)d_in[5];
    const float* kw = (const float*)d_in[6];
    const float* kb = (const float*)d_in[7];
    const float* vw = (const float*)d_in[8];
    const float* vb = (const float*)d_in[9];
    const float* ow = (const float*)d_in[10];
    const float* ob = (const float*)d_in[11];
    float* out = (float*)d_out;

    cudaFuncSetAttribute(gemm3_kernel,    cudaFuncAttributeMaxDynamicSharedMemorySize, GV_SM);
    cudaFuncSetAttribute(attn_mma_kernel, cudaFuncAttributeMaxDynamicSharedMemorySize, AT_SMEM);

    prep_all_kernel<<<512, 256>>>(qw, kw, vw, ow);
    gemm3_kernel<<<1536, 384, GV_SM>>>(query, key_t, value, qb, kb, vb);
    attn_mma_kernel<<<BNc, 256, AT_SMEM>>>(ob, out);
}